// round 1
// baseline (speedup 1.0000x reference)
#include <cuda_runtime.h>
#include <math.h>

// ---------------- problem constants ----------------
#define B_   2
#define L_   1024
#define DM   1024
#define DS   16
#define DFF  4096
#define DI   2048
#define DTR  64
#define BL   (B_*L_)          // 2048 rows (tokens)
#define XPN  (DTR + 2*DS)     // 96

// ---------------- scratch (device globals; no allocation allowed) ----------------
__device__ float g_xz  [BL * 2 * DI];   // in_proj output (x | z)
__device__ float g_xc  [BL * DI];       // conv+silu(x)
__device__ float g_xdbl[BL * XPN];      // x_proj output (dt|B|C)
__device__ float g_dt  [BL * DI];       // softplus(dt @ dt_proj^T + b)
__device__ float g_y   [BL * DI];       // gated scan output
__device__ float g_mam [BL * DM];       // out_proj output
__device__ float g_zm  [BL * DM];       // Z_mam (post first rmsnorm)
__device__ float g_h   [BL * DFF];      // MLP hidden
__device__ float g_mlp [BL * DM];       // MLP output

// ---------------- GEMM: C[M,N] = A[M,K] @ B[N,K]^T  (+bias, +activation) ----------------
// ACT: 0 = none, 1 = softplus, 2 = exact gelu
// BM=BN=128, BK=16, 256 threads, 8x8 per-thread microtile.
// Requirements honored by all call sites: M % 128 == 0, K % 16 == 0, rows
// of A/B 16B-aligned (lda/ldb multiples of 4). N may be ragged (x_proj N=96).
template<int ACT>
__global__ void sgemm_nt(const float* __restrict__ A, int lda,
                         const float* __restrict__ Bm, int ldb,
                         float* __restrict__ C, int ldc,
                         int N, int K,
                         const float* __restrict__ bias)
{
    __shared__ float As[16][132];
    __shared__ float Bs[16][132];

    const int tid = threadIdx.x;
    const int m0  = blockIdx.y * 128;
    const int n0  = blockIdx.x * 128;
    const int ty  = tid >> 4;     // 0..15
    const int tx  = tid & 15;     // 0..15

    float acc[8][8];
#pragma unroll
    for (int i = 0; i < 8; i++)
#pragma unroll
        for (int j = 0; j < 8; j++) acc[i][j] = 0.f;

    for (int k0 = 0; k0 < K; k0 += 16) {
        // cooperative tile loads: 128 rows x 16 cols, as float4 along K
#pragma unroll
        for (int i = 0; i < 2; i++) {
            int v   = tid + i * 256;        // 0..511
            int row = v >> 2;               // 0..127
            int c4  = (v & 3) << 2;         // 0,4,8,12

            float4 av = *(const float4*)(A + (size_t)(m0 + row) * lda + k0 + c4);
            As[c4 + 0][row] = av.x; As[c4 + 1][row] = av.y;
            As[c4 + 2][row] = av.z; As[c4 + 3][row] = av.w;

            int bn = n0 + row;
            float4 bv = make_float4(0.f, 0.f, 0.f, 0.f);
            if (bn < N)
                bv = *(const float4*)(Bm + (size_t)bn * ldb + k0 + c4);
            Bs[c4 + 0][row] = bv.x; Bs[c4 + 1][row] = bv.y;
            Bs[c4 + 2][row] = bv.z; Bs[c4 + 3][row] = bv.w;
        }
        __syncthreads();

#pragma unroll
        for (int kk = 0; kk < 16; kk++) {
            float a[8], b[8];
#pragma unroll
            for (int i = 0; i < 8; i++) a[i] = As[kk][ty * 8 + i];
#pragma unroll
            for (int j = 0; j < 8; j++) b[j] = Bs[kk][tx * 8 + j];
#pragma unroll
            for (int i = 0; i < 8; i++)
#pragma unroll
                for (int j = 0; j < 8; j++)
                    acc[i][j] = fmaf(a[i], b[j], acc[i][j]);
        }
        __syncthreads();
    }

    // epilogue
#pragma unroll
    for (int j = 0; j < 8; j++) {
        int n = n0 + tx * 8 + j;
        if (n >= N) continue;
        float bv = bias ? bias[n] : 0.f;
#pragma unroll
        for (int i = 0; i < 8; i++) {
            int m = m0 + ty * 8 + i;
            float v = acc[i][j] + bv;
            if (ACT == 1) {
                // stable softplus: max(v,0) + log1p(exp(-|v|))
                v = fmaxf(v, 0.f) + log1pf(expf(-fabsf(v)));
            } else if (ACT == 2) {
                // exact gelu
                v = 0.5f * v * (1.f + erff(v * 0.70710678118654752f));
            }
            C[(size_t)m * ldc + n] = v;
        }
    }
}

// ---------------- causal depthwise conv (K=4) + bias + SiLU ----------------
// x lives in the first DI columns of g_xz (row stride 2*DI)
__global__ void conv_silu_kernel(const float* __restrict__ conv_w,
                                 const float* __restrict__ conv_b)
{
    int idx = blockIdx.x * blockDim.x + threadIdx.x;
    if (idx >= BL * DI) return;
    int d  = idx % DI;
    int bl = idx / DI;
    int l  = bl % L_;

    float acc = conv_b[d];
#pragma unroll
    for (int j = 0; j < 4; j++) {
        int ls = l - 3 + j;
        if (ls >= 0)
            acc += g_xz[(size_t)(bl - (3 - j)) * (2 * DI) + d] * conv_w[d * 4 + j];
    }
    g_xc[idx] = acc / (1.f + __expf(-acc));     // silu
}

// ---------------- selective scan ----------------
// One 16-lane group per channel (b,d); lane s holds state s of DS=16.
// Fuses +x*D and *silu(z) gating into the output.
__global__ void scan_kernel(const float* __restrict__ A_log,
                            const float* __restrict__ Dp)
{
    const int tid = threadIdx.x;
    const int s   = tid & 15;
    const int cg  = blockIdx.x * 16 + (tid >> 4);   // 0..B_*DI-1
    const int b   = cg / DI;
    const int d   = cg % DI;

    const float a  = -expf(A_log[d * DS + s]);
    const float Dd = Dp[d];

    float h = 0.f;
    for (int l = 0; l < L_; l++) {
        const int bl = b * L_ + l;
        const float dtv = g_dt  [(size_t)bl * DI + d];
        const float xv  = g_xc  [(size_t)bl * DI + d];
        const float Bv  = g_xdbl[bl * XPN + DTR + s];
        const float Cv  = g_xdbl[bl * XPN + DTR + DS + s];

        h = expf(dtv * a) * h + dtv * Bv * xv;

        float p = h * Cv;
        p += __shfl_xor_sync(0xffffffffu, p, 8);
        p += __shfl_xor_sync(0xffffffffu, p, 4);
        p += __shfl_xor_sync(0xffffffffu, p, 2);
        p += __shfl_xor_sync(0xffffffffu, p, 1);

        if (s == 0) {
            float zv = g_xz[(size_t)bl * (2 * DI) + DI + d];
            float yv = p + xv * Dd;
            g_y[(size_t)bl * DI + d] = yv * (zv / (1.f + __expf(-zv)));
        }
    }
}

// ---------------- fused residual add + RMSNorm ----------------
// out[row] = (x+res) * rsqrt(mean((x+res)^2)+1e-6) * w ; one 256-thread block per row (DM=1024)
__global__ void rmsnorm_kernel(const float* __restrict__ x,
                               const float* __restrict__ res,
                               const float* __restrict__ w,
                               float* __restrict__ out)
{
    const int row = blockIdx.x;
    const int tid = threadIdx.x;

    float4 xv = ((const float4*)(x   + (size_t)row * DM))[tid];
    float4 rv = ((const float4*)(res + (size_t)row * DM))[tid];
    float v0 = xv.x + rv.x, v1 = xv.y + rv.y, v2 = xv.z + rv.z, v3 = xv.w + rv.w;

    float ss = v0 * v0 + v1 * v1 + v2 * v2 + v3 * v3;
#pragma unroll
    for (int m = 16; m; m >>= 1) ss += __shfl_xor_sync(0xffffffffu, ss, m);

    __shared__ float red[8];
    if ((tid & 31) == 0) red[tid >> 5] = ss;
    __syncthreads();
    if (tid < 8) {
        float t = red[tid];
#pragma unroll
        for (int m = 4; m; m >>= 1) t += __shfl_xor_sync(0xffu, t, m);
        if (tid == 0) red[0] = t;
    }
    __syncthreads();

    const float scale = rsqrtf(red[0] / (float)DM + 1e-6f);
    float4 wv = ((const float4*)w)[tid];
    float4 o;
    o.x = v0 * scale * wv.x; o.y = v1 * scale * wv.y;
    o.z = v2 * scale * wv.z; o.w = v3 * scale * wv.w;
    ((float4*)(out + (size_t)row * DM))[tid] = o;
}

// ---------------- launch ----------------
extern "C" void kernel_launch(void* const* d_in, const int* in_sizes, int n_in,
                              void* d_out, int out_size)
{
    const float* Z       = (const float*)d_in[0];
    const float* in_w    = (const float*)d_in[1];   // (2*DI, DM)
    const float* conv_w  = (const float*)d_in[2];   // (DI, 4)
    const float* conv_b  = (const float*)d_in[3];   // (DI,)
    const float* xproj_w = (const float*)d_in[4];   // (96, DI)
    const float* dtp_w   = (const float*)d_in[5];   // (DI, 64)
    const float* dtp_b   = (const float*)d_in[6];   // (DI,)
    const float* A_log   = (const float*)d_in[7];   // (DI, DS)
    const float* Dp      = (const float*)d_in[8];   // (DI,)
    const float* outp_w  = (const float*)d_in[9];   // (DM, DI)
    const float* w1      = (const float*)d_in[10];  // (DFF, DM)
    const float* b1      = (const float*)d_in[11];
    const float* w2      = (const float*)d_in[12];  // (DM, DFF)
    const float* b2      = (const float*)d_in[13];
    const float* nw      = (const float*)d_in[14];  // (DM,)
    float* out = (float*)d_out;

    float *xz, *xc, *xdbl, *dtb, *yb, *mam, *zm, *hb, *mlp;
    cudaGetSymbolAddress((void**)&xz,   g_xz);
    cudaGetSymbolAddress((void**)&xc,   g_xc);
    cudaGetSymbolAddress((void**)&xdbl, g_xdbl);
    cudaGetSymbolAddress((void**)&dtb,  g_dt);
    cudaGetSymbolAddress((void**)&yb,   g_y);
    cudaGetSymbolAddress((void**)&mam,  g_mam);
    cudaGetSymbolAddress((void**)&zm,   g_zm);
    cudaGetSymbolAddress((void**)&hb,   g_h);
    cudaGetSymbolAddress((void**)&mlp,  g_mlp);

    const dim3 thr(256);

    // 1) xz = Z @ in_proj_w^T            (2048 x 4096, K=1024)
    sgemm_nt<0><<<dim3(4096 / 128, BL / 128), thr>>>(Z, DM, in_w, DM, xz, 2 * DI, 2 * DI, DM, nullptr);

    // 2) x = silu(causal_dwconv(x) + b)
    conv_silu_kernel<<<(BL * DI + 255) / 256, thr>>>(conv_w, conv_b);

    // 3) x_dbl = x @ x_proj_w^T          (2048 x 96, K=2048)
    sgemm_nt<0><<<dim3(1, BL / 128), thr>>>(xc, DI, xproj_w, DI, xdbl, XPN, XPN, DI, nullptr);

    // 4) dt = softplus(dt_part @ dt_proj_w^T + dt_b)   (2048 x 2048, K=64; A lda=96)
    sgemm_nt<1><<<dim3(DI / 128, BL / 128), thr>>>(xdbl, XPN, dtp_w, DTR, dtb, DI, DI, DTR, dtp_b);

    // 5) selective scan (fused gating)
    scan_kernel<<<(B_ * DI) / 16, thr>>>(A_log, Dp);

    // 6) mamba_out = y @ out_proj_w^T    (2048 x 1024, K=2048)
    sgemm_nt<0><<<dim3(DM / 128, BL / 128), thr>>>(yb, DI, outp_w, DI, mam, DM, DM, DI, nullptr);

    // 7) Z_mam = rmsnorm(mamba_out + Z)
    rmsnorm_kernel<<<BL, thr>>>(mam, Z, nw, zm);

    // 8) h = gelu(Z_mam @ w1^T + b1)     (2048 x 4096, K=1024)
    sgemm_nt<2><<<dim3(DFF / 128, BL / 128), thr>>>(zm, DM, w1, DM, hb, DFF, DFF, DM, b1);

    // 9) mlp = h @ w2^T + b2             (2048 x 1024, K=4096)
    sgemm_nt<0><<<dim3(DM / 128, BL / 128), thr>>>(hb, DFF, w2, DFF, mlp, DM, DM, DFF, b2);

    // 10) out = rmsnorm(mlp + Z_mam)
    rmsnorm_kernel<<<BL, thr>>>(mlp, zm, nw, out);
}

// round 4
// speedup vs baseline: 1.2266x; 1.2266x over previous
#include <cuda_runtime.h>
#include <math.h>
#include <stdint.h>

// ---------------- problem constants ----------------
#define B_   2
#define L_   1024
#define DM   1024
#define DS   16
#define DFF  4096
#define DI   2048
#define DTR  64
#define BL   (B_*L_)          // 2048 rows (tokens)
#define XPN  (DTR + 2*DS)     // 96

// ---------------- scratch (device globals; no allocation allowed) ----------------
__device__ float g_xz  [BL * 2 * DI];   // in_proj output (x | z)
__device__ float g_xc  [BL * DI];       // conv+silu(x)
__device__ float g_xdbl[BL * XPN];      // x_proj output (dt|B|C)
__device__ float g_dt  [BL * DI];       // softplus(dt @ dt_proj^T + b)
__device__ float g_y   [BL * DI];       // gated scan output
__device__ float g_mam [BL * DM];       // out_proj output
__device__ float g_zm  [BL * DM];       // Z_mam (post first rmsnorm)
__device__ float g_h   [BL * DFF];      // MLP hidden
__device__ float g_mlp [BL * DM];       // MLP output

// ---------------- helpers ----------------
__device__ __forceinline__ float tf32_rna(float x) {
    uint32_t u;
    asm("cvt.rna.tf32.f32 %0, %1;" : "=r"(u) : "f"(x));
    return __uint_as_float(u);
}

#define MMA_TF32(d0,d1,d2,d3,a0,a1,a2,a3,b0,b1)                               \
    asm volatile(                                                             \
        "mma.sync.aligned.m16n8k8.row.col.f32.tf32.tf32.f32 "                 \
        "{%0,%1,%2,%3},{%4,%5,%6,%7},{%8,%9},{%0,%1,%2,%3};"                  \
        : "+f"(d0), "+f"(d1), "+f"(d2), "+f"(d3)                              \
        : "r"(a0), "r"(a1), "r"(a2), "r"(a3), "r"(b0), "r"(b1))

// ---------------- TF32 tensor-core GEMM ----------------
// C[M,N] = A[M,K] @ B[N,K]^T (+bias, +activation)
// ACT: 0 = none, 1 = softplus, 2 = exact gelu
// Block tile 128x128, K-tile 32, 256 threads = 8 warps (2 m x 4 n),
// warp tile 64x32, mma m16n8k8.tf32.
// Call-site contract: M % 128 == 0, K % 32 == 0, rows of A/B 16B-aligned.
// N may be ragged (guarded).
template<int ACT>
__global__ void __launch_bounds__(256, 2)
tc_gemm_nt(const float* __restrict__ A, int lda,
           const float* __restrict__ Bm, int ldb,
           float* __restrict__ C, int ldc,
           int N, int K,
           const float* __restrict__ bias)
{
    __shared__ float As[128][36];   // [m][k], pad 36 -> conflict-free frag loads
    __shared__ float Bs[128][36];   // [n][k]

    const int tid  = threadIdx.x;
    const int m0   = blockIdx.y * 128;
    const int n0   = blockIdx.x * 128;

    const int warp = tid >> 5;
    const int lane = tid & 31;
    const int wm   = (warp & 1) * 64;     // warp m-offset in block
    const int wn   = (warp >> 1) * 32;    // warp n-offset in block
    const int g    = lane >> 2;           // 0..7
    const int t    = lane & 3;            // 0..3

    float acc[4][4][4];
#pragma unroll
    for (int i = 0; i < 4; i++)
#pragma unroll
        for (int j = 0; j < 4; j++)
#pragma unroll
            for (int c = 0; c < 4; c++) acc[i][j][c] = 0.f;

    for (int k0 = 0; k0 < K; k0 += 32) {
        // ---- global -> smem (with tf32 rounding), 128x32 per tile ----
#pragma unroll
        for (int i = 0; i < 4; i++) {
            int v   = tid + i * 256;      // 0..1023
            int row = v >> 3;             // 0..127
            int kc  = (v & 7) << 2;       // 0,4,...,28

            float4 av = *(const float4*)(A + (size_t)(m0 + row) * lda + k0 + kc);
            av.x = tf32_rna(av.x); av.y = tf32_rna(av.y);
            av.z = tf32_rna(av.z); av.w = tf32_rna(av.w);
            *(float4*)&As[row][kc] = av;

            float4 bv = make_float4(0.f, 0.f, 0.f, 0.f);
            if (n0 + row < N) {
                bv = *(const float4*)(Bm + (size_t)(n0 + row) * ldb + k0 + kc);
                bv.x = tf32_rna(bv.x); bv.y = tf32_rna(bv.y);
                bv.z = tf32_rna(bv.z); bv.w = tf32_rna(bv.w);
            }
            *(float4*)&Bs[row][kc] = bv;
        }
        __syncthreads();

        // ---- 4 k-steps of 8 ----
#pragma unroll
        for (int ks = 0; ks < 4; ks++) {
            const int kb = ks * 8;

            uint32_t a[4][4];
#pragma unroll
            for (int mf = 0; mf < 4; mf++) {
                int r0 = wm + mf * 16 + g;
                a[mf][0] = __float_as_uint(As[r0    ][kb + t    ]);
                a[mf][1] = __float_as_uint(As[r0 + 8][kb + t    ]);
                a[mf][2] = __float_as_uint(As[r0    ][kb + t + 4]);
                a[mf][3] = __float_as_uint(As[r0 + 8][kb + t + 4]);
            }
            uint32_t b[4][2];
#pragma unroll
            for (int nf = 0; nf < 4; nf++) {
                int c0 = wn + nf * 8 + g;
                b[nf][0] = __float_as_uint(Bs[c0][kb + t    ]);
                b[nf][1] = __float_as_uint(Bs[c0][kb + t + 4]);
            }
#pragma unroll
            for (int mf = 0; mf < 4; mf++)
#pragma unroll
                for (int nf = 0; nf < 4; nf++)
                    MMA_TF32(acc[mf][nf][0], acc[mf][nf][1],
                             acc[mf][nf][2], acc[mf][nf][3],
                             a[mf][0], a[mf][1], a[mf][2], a[mf][3],
                             b[nf][0], b[nf][1]);
        }
        __syncthreads();
    }

    // ---- epilogue ----
#pragma unroll
    for (int nf = 0; nf < 4; nf++) {
        int col = n0 + wn + nf * 8 + t * 2;
        if (col >= N) continue;
        float bv0 = bias ? bias[col]     : 0.f;
        float bv1 = bias ? bias[col + 1] : 0.f;
#pragma unroll
        for (int mf = 0; mf < 4; mf++) {
            int row = m0 + wm + mf * 16 + g;
#pragma unroll
            for (int half = 0; half < 2; half++) {
                int r = row + half * 8;
                float v0 = acc[mf][nf][half * 2 + 0] + bv0;
                float v1 = acc[mf][nf][half * 2 + 1] + bv1;
                if (ACT == 1) {
                    v0 = fmaxf(v0, 0.f) + log1pf(expf(-fabsf(v0)));
                    v1 = fmaxf(v1, 0.f) + log1pf(expf(-fabsf(v1)));
                } else if (ACT == 2) {
                    v0 = 0.5f * v0 * (1.f + erff(v0 * 0.70710678118654752f));
                    v1 = 0.5f * v1 * (1.f + erff(v1 * 0.70710678118654752f));
                }
                *(float2*)(C + (size_t)r * ldc + col) = make_float2(v0, v1);
            }
        }
    }
}

// ---------------- causal depthwise conv (K=4) + bias + SiLU ----------------
__global__ void conv_silu_kernel(const float* __restrict__ conv_w,
                                 const float* __restrict__ conv_b)
{
    int idx = blockIdx.x * blockDim.x + threadIdx.x;
    if (idx >= BL * DI) return;
    int d  = idx % DI;
    int bl = idx / DI;
    int l  = bl % L_;

    float acc = conv_b[d];
#pragma unroll
    for (int j = 0; j < 4; j++) {
        int ls = l - 3 + j;
        if (ls >= 0)
            acc += g_xz[(size_t)(bl - (3 - j)) * (2 * DI) + d] * conv_w[d * 4 + j];
    }
    g_xc[idx] = acc / (1.f + __expf(-acc));     // silu
}

// ---------------- selective scan ----------------
__global__ void scan_kernel(const float* __restrict__ A_log,
                            const float* __restrict__ Dp)
{
    const int tid = threadIdx.x;
    const int s   = tid & 15;
    const int cg  = blockIdx.x * 16 + (tid >> 4);   // 0..B_*DI-1
    const int b   = cg / DI;
    const int d   = cg % DI;

    const float a  = -expf(A_log[d * DS + s]);
    const float Dd = Dp[d];

    float h = 0.f;
    for (int l = 0; l < L_; l++) {
        const int bl = b * L_ + l;
        const float dtv = g_dt  [(size_t)bl * DI + d];
        const float xv  = g_xc  [(size_t)bl * DI + d];
        const float Bv  = g_xdbl[bl * XPN + DTR + s];
        const float Cv  = g_xdbl[bl * XPN + DTR + DS + s];

        h = expf(dtv * a) * h + dtv * Bv * xv;

        float p = h * Cv;
        p += __shfl_xor_sync(0xffffffffu, p, 8);
        p += __shfl_xor_sync(0xffffffffu, p, 4);
        p += __shfl_xor_sync(0xffffffffu, p, 2);
        p += __shfl_xor_sync(0xffffffffu, p, 1);

        if (s == 0) {
            float zv = g_xz[(size_t)bl * (2 * DI) + DI + d];
            float yv = p + xv * Dd;
            g_y[(size_t)bl * DI + d] = yv * (zv / (1.f + __expf(-zv)));
        }
    }
}

// ---------------- fused residual add + RMSNorm ----------------
__global__ void rmsnorm_kernel(const float* __restrict__ x,
                               const float* __restrict__ res,
                               const float* __restrict__ w,
                               float* __restrict__ out)
{
    const int row = blockIdx.x;
    const int tid = threadIdx.x;

    float4 xv = ((const float4*)(x   + (size_t)row * DM))[tid];
    float4 rv = ((const float4*)(res + (size_t)row * DM))[tid];
    float v0 = xv.x + rv.x, v1 = xv.y + rv.y, v2 = xv.z + rv.z, v3 = xv.w + rv.w;

    float ss = v0 * v0 + v1 * v1 + v2 * v2 + v3 * v3;
#pragma unroll
    for (int m = 16; m; m >>= 1) ss += __shfl_xor_sync(0xffffffffu, ss, m);

    __shared__ float red[8];
    if ((tid & 31) == 0) red[tid >> 5] = ss;
    __syncthreads();
    if (tid < 8) {
        float tt = red[tid];
#pragma unroll
        for (int m = 4; m; m >>= 1) tt += __shfl_xor_sync(0xffu, tt, m);
        if (tid == 0) red[0] = tt;
    }
    __syncthreads();

    const float scale = rsqrtf(red[0] / (float)DM + 1e-6f);
    float4 wv = ((const float4*)w)[tid];
    float4 o;
    o.x = v0 * scale * wv.x; o.y = v1 * scale * wv.y;
    o.z = v2 * scale * wv.z; o.w = v3 * scale * wv.w;
    ((float4*)(out + (size_t)row * DM))[tid] = o;
}

// ---------------- launch ----------------
extern "C" void kernel_launch(void* const* d_in, const int* in_sizes, int n_in,
                              void* d_out, int out_size)
{
    const float* Z       = (const float*)d_in[0];
    const float* in_w    = (const float*)d_in[1];   // (2*DI, DM)
    const float* conv_w  = (const float*)d_in[2];   // (DI, 4)
    const float* conv_b  = (const float*)d_in[3];   // (DI,)
    const float* xproj_w = (const float*)d_in[4];   // (96, DI)
    const float* dtp_w   = (const float*)d_in[5];   // (DI, 64)
    const float* dtp_b   = (const float*)d_in[6];   // (DI,)
    const float* A_log   = (const float*)d_in[7];   // (DI, DS)
    const float* Dp      = (const float*)d_in[8];   // (DI,)
    const float* outp_w  = (const float*)d_in[9];   // (DM, DI)
    const float* w1      = (const float*)d_in[10];  // (DFF, DM)
    const float* b1      = (const float*)d_in[11];
    const float* w2      = (const float*)d_in[12];  // (DM, DFF)
    const float* b2      = (const float*)d_in[13];
    const float* nw      = (const float*)d_in[14];  // (DM,)
    float* out = (float*)d_out;

    float *xz, *xc, *xdbl, *dtb, *yb, *mam, *zm, *hb, *mlp;
    cudaGetSymbolAddress((void**)&xz,   g_xz);
    cudaGetSymbolAddress((void**)&xc,   g_xc);
    cudaGetSymbolAddress((void**)&xdbl, g_xdbl);
    cudaGetSymbolAddress((void**)&dtb,  g_dt);
    cudaGetSymbolAddress((void**)&yb,   g_y);
    cudaGetSymbolAddress((void**)&mam,  g_mam);
    cudaGetSymbolAddress((void**)&zm,   g_zm);
    cudaGetSymbolAddress((void**)&hb,   g_h);
    cudaGetSymbolAddress((void**)&mlp,  g_mlp);

    const dim3 thr(256);

    // 1) xz = Z @ in_proj_w^T            (2048 x 4096, K=1024)
    tc_gemm_nt<0><<<dim3(4096 / 128, BL / 128), thr>>>(Z, DM, in_w, DM, xz, 2 * DI, 2 * DI, DM, nullptr);

    // 2) x = silu(causal_dwconv(x) + b)
    conv_silu_kernel<<<(BL * DI + 255) / 256, thr>>>(conv_w, conv_b);

    // 3) x_dbl = x @ x_proj_w^T          (2048 x 96, K=2048)
    tc_gemm_nt<0><<<dim3(1, BL / 128), thr>>>(xc, DI, xproj_w, DI, xdbl, XPN, XPN, DI, nullptr);

    // 4) dt = softplus(dt_part @ dt_proj_w^T + dt_b)   (2048 x 2048, K=64; A lda=96)
    tc_gemm_nt<1><<<dim3(DI / 128, BL / 128), thr>>>(xdbl, XPN, dtp_w, DTR, dtb, DI, DI, DTR, dtp_b);

    // 5) selective scan (fused gating)
    scan_kernel<<<(B_ * DI) / 16, thr>>>(A_log, Dp);

    // 6) mamba_out = y @ out_proj_w^T    (2048 x 1024, K=2048)
    tc_gemm_nt<0><<<dim3(DM / 128, BL / 128), thr>>>(yb, DI, outp_w, DI, mam, DM, DM, DI, nullptr);

    // 7) Z_mam = rmsnorm(mamba_out + Z)
    rmsnorm_kernel<<<BL, thr>>>(mam, Z, nw, zm);

    // 8) h = gelu(Z_mam @ w1^T + b1)     (2048 x 4096, K=1024)
    tc_gemm_nt<2><<<dim3(DFF / 128, BL / 128), thr>>>(zm, DM, w1, DM, hb, DFF, DFF, DM, b1);

    // 9) mlp = h @ w2^T + b2             (2048 x 1024, K=4096)
    tc_gemm_nt<0><<<dim3(DM / 128, BL / 128), thr>>>(hb, DFF, w2, DFF, mlp, DM, DM, DFF, b2);

    // 10) out = rmsnorm(mlp + Z_mam)
    rmsnorm_kernel<<<BL, thr>>>(mlp, zm, nw, out);
}

// round 5
// speedup vs baseline: 1.9209x; 1.5660x over previous
#include <cuda_runtime.h>
#include <math.h>
#include <stdint.h>

// ---------------- problem constants ----------------
#define B_   2
#define L_   1024
#define DM   1024
#define DS   16
#define DFF  4096
#define DI   2048
#define DTR  64
#define BL   (B_*L_)          // 2048 rows (tokens)
#define XPN  (DTR + 2*DS)     // 96

// ---------------- scratch (device globals; no allocation allowed) ----------------
__device__ float g_xz  [BL * 2 * DI];   // in_proj output (x | z)
__device__ float g_xc  [BL * DI];       // conv+silu(x)
__device__ float g_xdbl[BL * XPN];      // x_proj output (dt|B|C)
__device__ float g_dt  [BL * DI];       // softplus(dt @ dt_proj^T + b)
__device__ float g_y   [BL * DI];       // gated scan output
__device__ float g_mam [BL * DM];       // out_proj output
__device__ float g_zm  [BL * DM];       // Z_mam (post first rmsnorm)
__device__ float g_h   [BL * DFF];      // MLP hidden
__device__ float g_mlp [BL * DM];       // MLP output

#define MMA_TF32(d0,d1,d2,d3,a0,a1,a2,a3,b0,b1)                               \
    asm volatile(                                                             \
        "mma.sync.aligned.m16n8k8.row.col.f32.tf32.tf32.f32 "                 \
        "{%0,%1,%2,%3},{%4,%5,%6,%7},{%8,%9},{%0,%1,%2,%3};"                  \
        : "+f"(d0), "+f"(d1), "+f"(d2), "+f"(d3)                              \
        : "r"(a0), "r"(a1), "r"(a2), "r"(a3), "r"(b0), "r"(b1))

#define CP_ASYNC16(dst, src)                                                   \
    asm volatile("cp.async.cg.shared.global [%0], [%1], 16;" :: "r"(dst), "l"(src))
#define CP_ASYNC16_Z(dst, src, sz)                                             \
    asm volatile("cp.async.cg.shared.global [%0], [%1], 16, %2;" :: "r"(dst), "l"(src), "r"(sz))

// smem: 2 stages x (A[128][36] + B[128][36]) floats
#define TILE_F   (128 * 36)
#define GEMM_SMEM_BYTES (2 * 2 * TILE_F * 4)

// ---------------- TF32 tensor-core GEMM, cp.async double-buffered ----------------
// C[M,N] = A[M,K] @ B[N,K]^T (+bias, +activation)
// ACT: 0 = none, 1 = softplus, 2 = exact gelu
// Block tile 128x128, K-tile 32, 256 threads = 8 warps (2m x 4n), warp tile 64x32.
// Contract: M % 128 == 0, K % 32 == 0, lda/ldb multiples of 4. N may be ragged.
// TF32 rounding is done by the MMA hardware (truncation of low mantissa bits).
template<int ACT>
__global__ void __launch_bounds__(256, 2)
tc_gemm_nt(const float* __restrict__ A, int lda,
           const float* __restrict__ Bm, int ldb,
           float* __restrict__ C, int ldc,
           int N, int K,
           const float* __restrict__ bias)
{
    extern __shared__ float sm[];
    // stage layout: [stage][A|B][128][36]
    float* const AsS[2] = { sm,              sm + 2 * TILE_F };
    float* const BsS[2] = { sm + TILE_F,     sm + 3 * TILE_F };

    const int tid  = threadIdx.x;
    const int m0   = blockIdx.y * 128;
    const int n0   = blockIdx.x * 128;

    const int warp = tid >> 5;
    const int lane = tid & 31;
    const int wm   = (warp & 1) * 64;     // warp m-offset in block
    const int wn   = (warp >> 1) * 32;    // warp n-offset in block
    const int g    = lane >> 2;           // 0..7
    const int t    = lane & 3;            // 0..3

    // per-thread copy coordinates (4 chunks of 16B per array per stage)
    const int crow = tid >> 3;            // 0..31  (+32 per chunk)
    const int ckc  = (tid & 7) << 2;      // 0,4,...,28

    float acc[4][4][4];
#pragma unroll
    for (int i = 0; i < 4; i++)
#pragma unroll
        for (int j = 0; j < 4; j++)
#pragma unroll
            for (int c = 0; c < 4; c++) acc[i][j][c] = 0.f;

    const int nIt = K >> 5;

    // ---- tile loader: issue 8 cp.async per thread, then commit ----
    auto load_tile = [&](int stage, int k0) {
        float* as = AsS[stage];
        float* bs = BsS[stage];
#pragma unroll
        for (int i = 0; i < 4; i++) {
            int row = crow + i * 32;
            uint32_t da = (uint32_t)__cvta_generic_to_shared(as + row * 36 + ckc);
            const float* ga = A + (size_t)(m0 + row) * lda + k0 + ckc;
            CP_ASYNC16(da, ga);

            int brow = n0 + row;
            uint32_t db = (uint32_t)__cvta_generic_to_shared(bs + row * 36 + ckc);
            const float* gb = Bm + (size_t)(brow < N ? brow : 0) * ldb + k0 + ckc;
            int sz = (brow < N) ? 16 : 0;
            CP_ASYNC16_Z(db, gb, sz);
        }
        asm volatile("cp.async.commit_group;");
    };

    load_tile(0, 0);

    for (int it = 0; it < nIt; ++it) {
        const int stage = it & 1;
        if (it + 1 < nIt) {
            load_tile((it + 1) & 1, (it + 1) << 5);
            asm volatile("cp.async.wait_group 1;");
        } else {
            asm volatile("cp.async.wait_group 0;");
        }
        __syncthreads();

        const float* as = AsS[stage];
        const float* bs = BsS[stage];

#pragma unroll
        for (int ks = 0; ks < 4; ks++) {
            const int kb = ks * 8;

            uint32_t a[4][4];
#pragma unroll
            for (int mf = 0; mf < 4; mf++) {
                int r0 = wm + mf * 16 + g;
                a[mf][0] = __float_as_uint(as[(r0    ) * 36 + kb + t    ]);
                a[mf][1] = __float_as_uint(as[(r0 + 8) * 36 + kb + t    ]);
                a[mf][2] = __float_as_uint(as[(r0    ) * 36 + kb + t + 4]);
                a[mf][3] = __float_as_uint(as[(r0 + 8) * 36 + kb + t + 4]);
            }
            uint32_t b[4][2];
#pragma unroll
            for (int nf = 0; nf < 4; nf++) {
                int c0 = wn + nf * 8 + g;
                b[nf][0] = __float_as_uint(bs[c0 * 36 + kb + t    ]);
                b[nf][1] = __float_as_uint(bs[c0 * 36 + kb + t + 4]);
            }
#pragma unroll
            for (int mf = 0; mf < 4; mf++)
#pragma unroll
                for (int nf = 0; nf < 4; nf++)
                    MMA_TF32(acc[mf][nf][0], acc[mf][nf][1],
                             acc[mf][nf][2], acc[mf][nf][3],
                             a[mf][0], a[mf][1], a[mf][2], a[mf][3],
                             b[nf][0], b[nf][1]);
        }
        __syncthreads();
    }

    // ---- epilogue ----
#pragma unroll
    for (int nf = 0; nf < 4; nf++) {
        int col = n0 + wn + nf * 8 + t * 2;
        if (col >= N) continue;
        float bv0 = bias ? bias[col]     : 0.f;
        float bv1 = bias ? bias[col + 1] : 0.f;
#pragma unroll
        for (int mf = 0; mf < 4; mf++) {
            int row = m0 + wm + mf * 16 + g;
#pragma unroll
            for (int half = 0; half < 2; half++) {
                int r = row + half * 8;
                float v0 = acc[mf][nf][half * 2 + 0] + bv0;
                float v1 = acc[mf][nf][half * 2 + 1] + bv1;
                if (ACT == 1) {
                    v0 = fmaxf(v0, 0.f) + log1pf(expf(-fabsf(v0)));
                    v1 = fmaxf(v1, 0.f) + log1pf(expf(-fabsf(v1)));
                } else if (ACT == 2) {
                    v0 = 0.5f * v0 * (1.f + erff(v0 * 0.70710678118654752f));
                    v1 = 0.5f * v1 * (1.f + erff(v1 * 0.70710678118654752f));
                }
                *(float2*)(C + (size_t)r * ldc + col) = make_float2(v0, v1);
            }
        }
    }
}

// ---------------- causal depthwise conv (K=4) + bias + SiLU ----------------
__global__ void conv_silu_kernel(const float* __restrict__ conv_w,
                                 const float* __restrict__ conv_b)
{
    int idx = blockIdx.x * blockDim.x + threadIdx.x;
    if (idx >= BL * DI) return;
    int d  = idx % DI;
    int bl = idx / DI;
    int l  = bl % L_;

    float acc = conv_b[d];
#pragma unroll
    for (int j = 0; j < 4; j++) {
        int ls = l - 3 + j;
        if (ls >= 0)
            acc += g_xz[(size_t)(bl - (3 - j)) * (2 * DI) + d] * conv_w[d * 4 + j];
    }
    g_xc[idx] = acc / (1.f + __expf(-acc));     // silu
}

// ---------------- selective scan ----------------
__global__ void scan_kernel(const float* __restrict__ A_log,
                            const float* __restrict__ Dp)
{
    const int tid = threadIdx.x;
    const int s   = tid & 15;
    const int cg  = blockIdx.x * 16 + (tid >> 4);   // 0..B_*DI-1
    const int b   = cg / DI;
    const int d   = cg % DI;

    const float a  = -expf(A_log[d * DS + s]);
    const float Dd = Dp[d];

    float h = 0.f;
    for (int l = 0; l < L_; l++) {
        const int bl = b * L_ + l;
        const float dtv = g_dt  [(size_t)bl * DI + d];
        const float xv  = g_xc  [(size_t)bl * DI + d];
        const float Bv  = g_xdbl[bl * XPN + DTR + s];
        const float Cv  = g_xdbl[bl * XPN + DTR + DS + s];

        h = expf(dtv * a) * h + dtv * Bv * xv;

        float p = h * Cv;
        p += __shfl_xor_sync(0xffffffffu, p, 8);
        p += __shfl_xor_sync(0xffffffffu, p, 4);
        p += __shfl_xor_sync(0xffffffffu, p, 2);
        p += __shfl_xor_sync(0xffffffffu, p, 1);

        if (s == 0) {
            float zv = g_xz[(size_t)bl * (2 * DI) + DI + d];
            float yv = p + xv * Dd;
            g_y[(size_t)bl * DI + d] = yv * (zv / (1.f + __expf(-zv)));
        }
    }
}

// ---------------- fused residual add + RMSNorm ----------------
__global__ void rmsnorm_kernel(const float* __restrict__ x,
                               const float* __restrict__ res,
                               const float* __restrict__ w,
                               float* __restrict__ out)
{
    const int row = blockIdx.x;
    const int tid = threadIdx.x;

    float4 xv = ((const float4*)(x   + (size_t)row * DM))[tid];
    float4 rv = ((const float4*)(res + (size_t)row * DM))[tid];
    float v0 = xv.x + rv.x, v1 = xv.y + rv.y, v2 = xv.z + rv.z, v3 = xv.w + rv.w;

    float ss = v0 * v0 + v1 * v1 + v2 * v2 + v3 * v3;
#pragma unroll
    for (int m = 16; m; m >>= 1) ss += __shfl_xor_sync(0xffffffffu, ss, m);

    __shared__ float red[8];
    if ((tid & 31) == 0) red[tid >> 5] = ss;
    __syncthreads();
    if (tid < 8) {
        float tt = red[tid];
#pragma unroll
        for (int m = 4; m; m >>= 1) tt += __shfl_xor_sync(0xffu, tt, m);
        if (tid == 0) red[0] = tt;
    }
    __syncthreads();

    const float scale = rsqrtf(red[0] / (float)DM + 1e-6f);
    float4 wv = ((const float4*)w)[tid];
    float4 o;
    o.x = v0 * scale * wv.x; o.y = v1 * scale * wv.y;
    o.z = v2 * scale * wv.z; o.w = v3 * scale * wv.w;
    ((float4*)(out + (size_t)row * DM))[tid] = o;
}

// ---------------- launch ----------------
extern "C" void kernel_launch(void* const* d_in, const int* in_sizes, int n_in,
                              void* d_out, int out_size)
{
    const float* Z       = (const float*)d_in[0];
    const float* in_w    = (const float*)d_in[1];   // (2*DI, DM)
    const float* conv_w  = (const float*)d_in[2];   // (DI, 4)
    const float* conv_b  = (const float*)d_in[3];   // (DI,)
    const float* xproj_w = (const float*)d_in[4];   // (96, DI)
    const float* dtp_w   = (const float*)d_in[5];   // (DI, 64)
    const float* dtp_b   = (const float*)d_in[6];   // (DI,)
    const float* A_log   = (const float*)d_in[7];   // (DI, DS)
    const float* Dp      = (const float*)d_in[8];   // (DI,)
    const float* outp_w  = (const float*)d_in[9];   // (DM, DI)
    const float* w1      = (const float*)d_in[10];  // (DFF, DM)
    const float* b1      = (const float*)d_in[11];
    const float* w2      = (const float*)d_in[12];  // (DM, DFF)
    const float* b2      = (const float*)d_in[13];
    const float* nw      = (const float*)d_in[14];  // (DM,)
    float* out = (float*)d_out;

    float *xz, *xc, *xdbl, *dtb, *yb, *mam, *zm, *hb, *mlp;
    cudaGetSymbolAddress((void**)&xz,   g_xz);
    cudaGetSymbolAddress((void**)&xc,   g_xc);
    cudaGetSymbolAddress((void**)&xdbl, g_xdbl);
    cudaGetSymbolAddress((void**)&dtb,  g_dt);
    cudaGetSymbolAddress((void**)&yb,   g_y);
    cudaGetSymbolAddress((void**)&mam,  g_mam);
    cudaGetSymbolAddress((void**)&zm,   g_zm);
    cudaGetSymbolAddress((void**)&hb,   g_h);
    cudaGetSymbolAddress((void**)&mlp,  g_mlp);

    // allow >48KB dynamic smem for the GEMM kernels (host attr; not a stream op)
    cudaFuncSetAttribute(tc_gemm_nt<0>, cudaFuncAttributeMaxDynamicSharedMemorySize, GEMM_SMEM_BYTES);
    cudaFuncSetAttribute(tc_gemm_nt<1>, cudaFuncAttributeMaxDynamicSharedMemorySize, GEMM_SMEM_BYTES);
    cudaFuncSetAttribute(tc_gemm_nt<2>, cudaFuncAttributeMaxDynamicSharedMemorySize, GEMM_SMEM_BYTES);

    const dim3 thr(256);
    const int  SB = GEMM_SMEM_BYTES;

    // 1) xz = Z @ in_proj_w^T            (2048 x 4096, K=1024)
    tc_gemm_nt<0><<<dim3(4096 / 128, BL / 128), thr, SB>>>(Z, DM, in_w, DM, xz, 2 * DI, 2 * DI, DM, nullptr);

    // 2) x = silu(causal_dwconv(x) + b)
    conv_silu_kernel<<<(BL * DI + 255) / 256, thr>>>(conv_w, conv_b);

    // 3) x_dbl = x @ x_proj_w^T          (2048 x 96, K=2048)
    tc_gemm_nt<0><<<dim3(1, BL / 128), thr, SB>>>(xc, DI, xproj_w, DI, xdbl, XPN, XPN, DI, nullptr);

    // 4) dt = softplus(dt_part @ dt_proj_w^T + dt_b)   (2048 x 2048, K=64; A lda=96)
    tc_gemm_nt<1><<<dim3(DI / 128, BL / 128), thr, SB>>>(xdbl, XPN, dtp_w, DTR, dtb, DI, DI, DTR, dtp_b);

    // 5) selective scan (fused gating)
    scan_kernel<<<(B_ * DI) / 16, thr>>>(A_log, Dp);

    // 6) mamba_out = y @ out_proj_w^T    (2048 x 1024, K=2048)
    tc_gemm_nt<0><<<dim3(DM / 128, BL / 128), thr, SB>>>(yb, DI, outp_w, DI, mam, DM, DM, DI, nullptr);

    // 7) Z_mam = rmsnorm(mamba_out + Z)
    rmsnorm_kernel<<<BL, thr>>>(mam, Z, nw, zm);

    // 8) h = gelu(Z_mam @ w1^T + b1)     (2048 x 4096, K=1024)
    tc_gemm_nt<2><<<dim3(DFF / 128, BL / 128), thr, SB>>>(zm, DM, w1, DM, hb, DFF, DFF, DM, b1);

    // 9) mlp = h @ w2^T + b2             (2048 x 1024, K=4096)
    tc_gemm_nt<0><<<dim3(DM / 128, BL / 128), thr, SB>>>(hb, DFF, w2, DFF, mlp, DM, DM, DFF, b2);

    // 10) out = rmsnorm(mlp + Z_mam)
    rmsnorm_kernel<<<BL, thr>>>(mlp, zm, nw, out);
}